// round 1
// baseline (speedup 1.0000x reference)
#include <cuda_runtime.h>
#include <math.h>

#define KCOMP 64
#define DDIM 8
#define NC 36      // packed lower-tri entries
#define NF 44      // features: 36 pair products + 8 linear
#define NW 48      // padded weight row (44 feats + 1 const + pad)

// scratch (no allocations allowed)
__device__ float  g_W[KCOMP * NW];
__device__ double g_bsum[2048];

// ---------------------------------------------------------------------------
// Preprocess: per component k, build the 45-coefficient affine/quadratic form
// lp(t) = w[44] + sum_j f[j] * w[j]
// where f = [t_a*t_b (a<=b), t_a].
// ---------------------------------------------------------------------------
__global__ void prep_kernel(const float* __restrict__ mu,
                            const float* __restrict__ Lc) {
    int k = threadIdx.x;
    if (k >= KCOMP) return;

    float L[DDIM][DDIM];
    {
        int idx = 0;
        #pragma unroll
        for (int i = 0; i < DDIM; ++i)
            #pragma unroll
            for (int j = 0; j <= i; ++j)
                L[i][j] = Lc[k * NC + idx++];
    }

    float logdet = 0.f;
    #pragma unroll
    for (int i = 0; i < DDIM; ++i) logdet += logf(L[i][i]);

    // A = inv(L) (lower triangular), forward substitution
    float A[DDIM][DDIM];
    #pragma unroll
    for (int i = 0; i < DDIM; ++i)
        #pragma unroll
        for (int j = 0; j < DDIM; ++j) A[i][j] = 0.f;

    #pragma unroll
    for (int j = 0; j < DDIM; ++j) {
        A[j][j] = 1.f / L[j][j];
        #pragma unroll
        for (int i = j + 1; i < DDIM; ++i) {
            float s = 0.f;
            #pragma unroll
            for (int mm = j; mm < i; ++mm) s += L[i][mm] * A[mm][j];
            A[i][j] = -s / L[i][i];
        }
    }

    float mv[DDIM];
    #pragma unroll
    for (int j = 0; j < DDIM; ++j) mv[j] = mu[k * DDIM + j];

    // v = A * mu
    float v[DDIM];
    #pragma unroll
    for (int i = 0; i < DDIM; ++i) {
        float s = 0.f;
        #pragma unroll
        for (int j = 0; j <= i; ++j) s += A[i][j] * mv[j];
        v[i] = s;
    }
    // q = A^T v  (= P * mu)
    float q[DDIM];
    #pragma unroll
    for (int a = 0; a < DDIM; ++a) {
        float s = 0.f;
        #pragma unroll
        for (int i = a; i < DDIM; ++i) s += A[i][a] * v[i];
        q[a] = s;
    }
    float c = 0.f;
    #pragma unroll
    for (int i = 0; i < DDIM; ++i) c += v[i] * v[i];

    float* w = g_W + k * NW;
    int p = 0;
    #pragma unroll
    for (int a = 0; a < DDIM; ++a) {
        #pragma unroll
        for (int b = a; b < DDIM; ++b) {
            float P = 0.f;
            #pragma unroll
            for (int i = b; i < DDIM; ++i) P += A[i][a] * A[i][b];
            w[p++] = (a == b) ? -0.5f * P : -P;   // fold factor 2 of off-diag
        }
    }
    #pragma unroll
    for (int a = 0; a < DDIM; ++a) w[NC + a] = q[a];

    const float NORM_CONST = -0.5f * (float)DDIM * 1.8378770664093453f; // log(2*pi)
    w[NF] = NORM_CONST - logdet - 0.5f * c;
    w[45] = 0.f; w[46] = 0.f; w[47] = 0.f;
}

// ---------------------------------------------------------------------------
// Main: one thread per sample. lp_k via 45-term dot against shared weight
// table, then logsumexp with pi folded into the exp (no per-element log).
// ---------------------------------------------------------------------------
__global__ void __launch_bounds__(256) mdn_kernel(
    const float* __restrict__ pi,
    const float* __restrict__ target,
    int B) {

    __shared__ float sW[KCOMP * NW];
    for (int i = threadIdx.x; i < (KCOMP * NW) / 4; i += blockDim.x)
        reinterpret_cast<float4*>(sW)[i] = reinterpret_cast<const float4*>(g_W)[i];
    __syncthreads();

    int b = blockIdx.x * blockDim.x + threadIdx.x;
    float lse = 0.f;
    if (b < B) {
        float4 t0 = reinterpret_cast<const float4*>(target)[b * 2 + 0];
        float4 t1 = reinterpret_cast<const float4*>(target)[b * 2 + 1];
        float t[DDIM] = {t0.x, t0.y, t0.z, t0.w, t1.x, t1.y, t1.z, t1.w};

        float f[NF];
        {
            int p = 0;
            #pragma unroll
            for (int a = 0; a < DDIM; ++a)
                #pragma unroll
                for (int b2 = a; b2 < DDIM; ++b2) f[p++] = t[a] * t[b2];
            #pragma unroll
            for (int a = 0; a < DDIM; ++a) f[NC + a] = t[a];
        }

        float lp[KCOMP];
        #pragma unroll
        for (int k = 0; k < KCOMP; ++k) {
            const float* w = sW + k * NW;
            float acc = w[NF];
            #pragma unroll
            for (int j = 0; j < NF; ++j) acc = fmaf(f[j], w[j], acc);
            lp[k] = acc;
        }

        float m = lp[0];
        #pragma unroll
        for (int k = 1; k < KCOMP; ++k) m = fmaxf(m, lp[k]);

        float S = 0.f;
        #pragma unroll
        for (int k4 = 0; k4 < KCOMP / 4; ++k4) {
            float4 pv = reinterpret_cast<const float4*>(pi)[b * (KCOMP / 4) + k4];
            S += (pv.x + 1e-10f) * __expf(lp[4 * k4 + 0] - m);
            S += (pv.y + 1e-10f) * __expf(lp[4 * k4 + 1] - m);
            S += (pv.z + 1e-10f) * __expf(lp[4 * k4 + 2] - m);
            S += (pv.w + 1e-10f) * __expf(lp[4 * k4 + 3] - m);
        }
        lse = m + logf(S);
    }

    // deterministic in-block tree reduction (double)
    __shared__ double red[256];
    red[threadIdx.x] = (double)lse;
    __syncthreads();
    #pragma unroll
    for (int s = 128; s > 0; s >>= 1) {
        if (threadIdx.x < (unsigned)s) red[threadIdx.x] += red[threadIdx.x + s];
        __syncthreads();
    }
    if (threadIdx.x == 0) g_bsum[blockIdx.x] = red[0];
}

__global__ void finish_kernel(float* __restrict__ out, int nblocks, int B) {
    __shared__ double red[512];
    double s = 0.0;
    for (int i = threadIdx.x; i < nblocks; i += blockDim.x) s += g_bsum[i];
    red[threadIdx.x] = s;
    __syncthreads();
    #pragma unroll
    for (int st = 256; st > 0; st >>= 1) {
        if (threadIdx.x < (unsigned)st) red[threadIdx.x] += red[threadIdx.x + st];
        __syncthreads();
    }
    if (threadIdx.x == 0) out[0] = (float)(-red[0] / (double)B);
}

extern "C" void kernel_launch(void* const* d_in, const int* in_sizes, int n_in,
                              void* d_out, int out_size) {
    const float* pi     = (const float*)d_in[0];   // (B, 64)
    const float* mu     = (const float*)d_in[1];   // (64, 8)
    const float* Lc     = (const float*)d_in[2];   // (64, 36)
    const float* target = (const float*)d_in[3];   // (B, 8)

    int B = in_sizes[0] / KCOMP;

    prep_kernel<<<1, KCOMP>>>(mu, Lc);

    int grid = (B + 255) / 256;
    if (grid > 2048) grid = 2048;  // fixed problem: B=131072 -> 512 blocks
    mdn_kernel<<<grid, 256>>>(pi, target, B);

    finish_kernel<<<1, 512>>>((float*)d_out, grid, B);
}

// round 2
// speedup vs baseline: 1.0526x; 1.0526x over previous
#include <cuda_runtime.h>
#include <math.h>
#include <float.h>

#define KCOMP 64
#define DDIM 8
#define NC 36      // packed lower-tri entries
#define NF 44      // features: 36 pair products + 8 linear
#define NW 48      // padded weight row (44 feats + 1 const + 3 pad)
#define TPB 256

// scratch (no allocations allowed)
__device__ float  g_W[KCOMP * NW];
__device__ double g_bsum[4096];

// ---------------------------------------------------------------------------
// f32x2 helpers (Blackwell packed fp32; PTX-only path)
// ---------------------------------------------------------------------------
__device__ __forceinline__ unsigned long long pack2(float lo, float hi) {
    unsigned long long r;
    asm("mov.b64 %0, {%1, %2};" : "=l"(r) : "f"(lo), "f"(hi));
    return r;
}
__device__ __forceinline__ void fma2(unsigned long long& d,
                                     unsigned long long a,
                                     unsigned long long b) {
    asm("fma.rn.f32x2 %0, %1, %2, %0;" : "+l"(d) : "l"(a), "l"(b));
}
__device__ __forceinline__ float sum2(unsigned long long a) {
    float lo, hi;
    asm("mov.b64 {%0, %1}, %2;" : "=f"(lo), "=f"(hi) : "l"(a));
    return lo + hi;
}

// ---------------------------------------------------------------------------
// Preprocess: per component k, build the 45-coefficient quadratic form
// lp(t) = w[44] + sum_j f[j]*w[j],  f = [t_a*t_b (a<=b), t_a].
// launch_bounds(64,1): let ptxas keep L and A fully in registers (no spills).
// ---------------------------------------------------------------------------
__global__ void __launch_bounds__(64, 1) prep_kernel(const float* __restrict__ mu,
                                                     const float* __restrict__ Lc) {
    int k = threadIdx.x;
    if (k >= KCOMP) return;

    float L[DDIM][DDIM];
    {
        int idx = 0;
        #pragma unroll
        for (int i = 0; i < DDIM; ++i)
            #pragma unroll
            for (int j = 0; j <= i; ++j)
                L[i][j] = Lc[k * NC + idx++];
    }

    float logdet = 0.f;
    #pragma unroll
    for (int i = 0; i < DDIM; ++i) logdet += logf(L[i][i]);

    // A = inv(L) (lower triangular), forward substitution
    float A[DDIM][DDIM];
    #pragma unroll
    for (int i = 0; i < DDIM; ++i)
        #pragma unroll
        for (int j = 0; j < DDIM; ++j) A[i][j] = 0.f;

    #pragma unroll
    for (int j = 0; j < DDIM; ++j) {
        A[j][j] = 1.f / L[j][j];
        #pragma unroll
        for (int i = j + 1; i < DDIM; ++i) {
            float s = 0.f;
            #pragma unroll
            for (int mm = j; mm < i; ++mm) s += L[i][mm] * A[mm][j];
            A[i][j] = -s / L[i][i];
        }
    }

    float mv[DDIM];
    #pragma unroll
    for (int j = 0; j < DDIM; ++j) mv[j] = mu[k * DDIM + j];

    // v = A * mu
    float v[DDIM];
    #pragma unroll
    for (int i = 0; i < DDIM; ++i) {
        float s = 0.f;
        #pragma unroll
        for (int j = 0; j <= i; ++j) s += A[i][j] * mv[j];
        v[i] = s;
    }
    // q = A^T v  (= P * mu)
    float q[DDIM];
    #pragma unroll
    for (int a = 0; a < DDIM; ++a) {
        float s = 0.f;
        #pragma unroll
        for (int i = a; i < DDIM; ++i) s += A[i][a] * v[i];
        q[a] = s;
    }
    float c = 0.f;
    #pragma unroll
    for (int i = 0; i < DDIM; ++i) c += v[i] * v[i];

    float* w = g_W + k * NW;
    int p = 0;
    #pragma unroll
    for (int a = 0; a < DDIM; ++a) {
        #pragma unroll
        for (int b = a; b < DDIM; ++b) {
            float P = 0.f;
            #pragma unroll
            for (int i = b; i < DDIM; ++i) P += A[i][a] * A[i][b];
            w[p++] = (a == b) ? -0.5f * P : -P;   // fold factor 2 of off-diag
        }
    }
    #pragma unroll
    for (int a = 0; a < DDIM; ++a) w[NC + a] = q[a];

    const float NORM_CONST = -0.5f * (float)DDIM * 1.8378770664093453f; // D*log(2*pi)
    w[NF] = NORM_CONST - logdet - 0.5f * c;
    w[45] = 0.f; w[46] = 0.f; w[47] = 0.f;
}

// ---------------------------------------------------------------------------
// Main kernel. One thread per sample.
//   - f32x2 packed 44-term dot products against shared weight table
//   - chunked online logsumexp (chunk = 32 components) -> no lp[64] array
//   - pi staged through shared with coalesced 128B loads (kills 8x L1 amp)
// ---------------------------------------------------------------------------
__global__ void __launch_bounds__(TPB, 2) mdn_kernel(
    const float* __restrict__ pi,
    const float* __restrict__ target,
    int B) {

    __shared__ float  sW[KCOMP * NW];          // 12 KB
    __shared__ float  sPi[TPB * 33];           // 33 KB (pad 33: conflict-free)
    __shared__ double red[TPB];                //  2 KB

    const int tid = threadIdx.x;
    const int b0  = blockIdx.x * TPB;
    const int b   = b0 + tid;
    const bool valid = (b < B);

    // weight table -> shared (float4)
    #pragma unroll
    for (int i = tid; i < (KCOMP * NW) / 4; i += TPB)
        reinterpret_cast<float4*>(sW)[i] = reinterpret_cast<const float4*>(g_W)[i];

    // per-sample features, packed as f32x2 pairs
    unsigned long long f2[NF / 2];
    {
        int bb = valid ? b : 0;
        float4 t0 = reinterpret_cast<const float4*>(target)[bb * 2 + 0];
        float4 t1 = reinterpret_cast<const float4*>(target)[bb * 2 + 1];
        float t[DDIM] = {t0.x, t0.y, t0.z, t0.w, t1.x, t1.y, t1.z, t1.w};

        float f[NF];
        int p = 0;
        #pragma unroll
        for (int a = 0; a < DDIM; ++a)
            #pragma unroll
            for (int b2 = a; b2 < DDIM; ++b2) f[p++] = t[a] * t[b2];
        #pragma unroll
        for (int a = 0; a < DDIM; ++a) f[NC + a] = t[a];

        #pragma unroll
        for (int j = 0; j < NF / 2; ++j) f2[j] = pack2(f[2 * j], f[2 * j + 1]);
    }

    float m = -FLT_MAX;
    float S = 0.f;

    #pragma unroll
    for (int c = 0; c < 2; ++c) {
        // ---- stage pi[:, c*32 : c*32+32] for this block's 256 samples ----
        __syncthreads();   // sPi free (and on c==0: sW writes done before use)
        #pragma unroll
        for (int q = tid; q < TPB * 8; q += TPB) {
            int s = q >> 3, e = q & 7;            // sample-in-block, float4-in-row
            int gs = b0 + s;
            float4 v = make_float4(0.f, 0.f, 0.f, 0.f);
            if (gs < B)
                v = reinterpret_cast<const float4*>(pi)[gs * (KCOMP / 4) + c * 8 + e];
            sPi[s * 33 + e * 4 + 0] = v.x;
            sPi[s * 33 + e * 4 + 1] = v.y;
            sPi[s * 33 + e * 4 + 2] = v.z;
            sPi[s * 33 + e * 4 + 3] = v.w;
        }
        __syncthreads();

        // ---- lp for 32 components of this chunk ----
        float lpc[32];
        float cmax = -FLT_MAX;
        #pragma unroll 4
        for (int kk = 0; kk < 32; ++kk) {
            const int k = c * 32 + kk;
            const ulonglong2* w2 = reinterpret_cast<const ulonglong2*>(sW + k * NW);
            unsigned long long acc0 = 0ull, acc1 = 0ull;   // {0.f,0.f}
            #pragma unroll
            for (int j2 = 0; j2 < 11; ++j2) {
                ulonglong2 ww = w2[j2];
                fma2(acc0, f2[2 * j2 + 0], ww.x);
                fma2(acc1, f2[2 * j2 + 1], ww.y);
            }
            float lp = sum2(acc0) + sum2(acc1) + sW[k * NW + NF];
            lpc[kk] = lp;
            cmax = fmaxf(cmax, lp);
        }

        // ---- online logsumexp fold, pi from shared (conflict-free rows) ----
        float mn = fmaxf(m, cmax);
        float Sn = S * __expf(m - mn);
        #pragma unroll 8
        for (int kk = 0; kk < 32; ++kk)
            Sn = fmaf(sPi[tid * 33 + kk] + 1e-10f, __expf(lpc[kk] - mn), Sn);
        m = mn;
        S = Sn;
    }

    float lse = valid ? (m + logf(S)) : 0.f;

    // deterministic in-block tree reduction (double)
    red[tid] = (double)lse;
    __syncthreads();
    #pragma unroll
    for (int s = TPB / 2; s > 0; s >>= 1) {
        if (tid < s) red[tid] += red[tid + s];
        __syncthreads();
    }
    if (tid == 0) g_bsum[blockIdx.x] = red[0];
}

__global__ void __launch_bounds__(512) finish_kernel(float* __restrict__ out,
                                                     int nblocks, int B) {
    __shared__ double red[512];
    double s = 0.0;
    for (int i = threadIdx.x; i < nblocks; i += 512) s += g_bsum[i];
    red[threadIdx.x] = s;
    __syncthreads();
    #pragma unroll
    for (int st = 256; st > 0; st >>= 1) {
        if (threadIdx.x < (unsigned)st) red[threadIdx.x] += red[threadIdx.x + st];
        __syncthreads();
    }
    if (threadIdx.x == 0) out[0] = (float)(-red[0] / (double)B);
}

extern "C" void kernel_launch(void* const* d_in, const int* in_sizes, int n_in,
                              void* d_out, int out_size) {
    const float* pi     = (const float*)d_in[0];   // (B, 64)
    const float* mu     = (const float*)d_in[1];   // (64, 8)
    const float* Lc     = (const float*)d_in[2];   // (64, 36)
    const float* target = (const float*)d_in[3];   // (B, 8)

    int B = in_sizes[0] / KCOMP;

    prep_kernel<<<1, KCOMP>>>(mu, Lc);

    int grid = (B + TPB - 1) / TPB;
    if (grid > 4096) grid = 4096;   // B=131072 -> 512 blocks; bound g_bsum
    mdn_kernel<<<grid, TPB>>>(pi, target, B);

    finish_kernel<<<1, 512>>>((float*)d_out, grid, B);
}

// round 3
// speedup vs baseline: 1.1404x; 1.0833x over previous
#include <cuda_runtime.h>
#include <math.h>
#include <float.h>

#define KCOMP 64
#define DDIM 8
#define NC 36      // packed lower-tri entries
#define NF 44      // features: 36 pair products + 8 linear
#define NW 48      // padded weight row (44 feats + 1 const + 3 pad)
#define TPB 256

// scratch (no allocations allowed)
__device__ float    g_W[KCOMP * NW];
__device__ double   g_bsum[4096];
__device__ unsigned g_done = 0;

// tril index helper (constant-folds under full unroll)
__device__ __forceinline__ constexpr int TIX(int i, int j) { return i * (i + 1) / 2 + j; }

// ---------------------------------------------------------------------------
// f32x2 helpers (Blackwell packed fp32; PTX-only path)
// ---------------------------------------------------------------------------
__device__ __forceinline__ unsigned long long pack2(float lo, float hi) {
    unsigned long long r;
    asm("mov.b64 %0, {%1, %2};" : "=l"(r) : "f"(lo), "f"(hi));
    return r;
}
__device__ __forceinline__ void fma2(unsigned long long& d,
                                     unsigned long long a,
                                     unsigned long long b) {
    asm("fma.rn.f32x2 %0, %1, %2, %0;" : "+l"(d) : "l"(a), "l"(b));
}
__device__ __forceinline__ float sum2(unsigned long long a) {
    float lo, hi;
    asm("mov.b64 {%0, %1}, %2;" : "=f"(lo), "=f"(hi) : "l"(a));
    return lo + hi;
}

// ---------------------------------------------------------------------------
// Preprocess (packed tril, register-resident): per component k build
// lp(t) = w[44] + sum_j f[j]*w[j],  f = [t_a*t_b (a<=b), t_a].
// ---------------------------------------------------------------------------
__global__ void __launch_bounds__(64, 1) prep_kernel(const float* __restrict__ mu,
                                                     const float* __restrict__ Lc) {
    int k = threadIdx.x;
    if (k >= KCOMP) return;

    float L[NC];
    #pragma unroll
    for (int i = 0; i < NC; ++i) L[i] = Lc[k * NC + i];

    float logdet = 0.f;
    #pragma unroll
    for (int i = 0; i < DDIM; ++i) logdet += logf(L[TIX(i, i)]);

    float dinv[DDIM];
    #pragma unroll
    for (int i = 0; i < DDIM; ++i) dinv[i] = 1.f / L[TIX(i, i)];

    // A = inv(L), lower triangular, packed tril
    float A[NC];
    #pragma unroll
    for (int j = 0; j < DDIM; ++j) {
        A[TIX(j, j)] = dinv[j];
        #pragma unroll
        for (int i = j + 1; i < DDIM; ++i) {
            float s = 0.f;
            #pragma unroll
            for (int mm = j; mm < i; ++mm) s += L[TIX(i, mm)] * A[TIX(mm, j)];
            A[TIX(i, j)] = -s * dinv[i];
        }
    }

    float mv[DDIM];
    #pragma unroll
    for (int j = 0; j < DDIM; ++j) mv[j] = mu[k * DDIM + j];

    // v = A * mu
    float v[DDIM];
    #pragma unroll
    for (int i = 0; i < DDIM; ++i) {
        float s = 0.f;
        #pragma unroll
        for (int j = 0; j <= i; ++j) s += A[TIX(i, j)] * mv[j];
        v[i] = s;
    }
    // q = A^T v  (= P * mu)
    float q[DDIM];
    #pragma unroll
    for (int a = 0; a < DDIM; ++a) {
        float s = 0.f;
        #pragma unroll
        for (int i = a; i < DDIM; ++i) s += A[TIX(i, a)] * v[i];
        q[a] = s;
    }
    float c = 0.f;
    #pragma unroll
    for (int i = 0; i < DDIM; ++i) c += v[i] * v[i];

    float* w = g_W + k * NW;
    int p = 0;
    #pragma unroll
    for (int a = 0; a < DDIM; ++a) {
        #pragma unroll
        for (int b = a; b < DDIM; ++b) {
            float P = 0.f;
            #pragma unroll
            for (int i = b; i < DDIM; ++i) P += A[TIX(i, a)] * A[TIX(i, b)];
            w[p++] = (a == b) ? -0.5f * P : -P;   // fold factor 2 of off-diag
        }
    }
    #pragma unroll
    for (int a = 0; a < DDIM; ++a) w[NC + a] = q[a];

    const float NORM_CONST = -0.5f * (float)DDIM * 1.8378770664093453f; // D*log(2*pi)
    w[NF] = NORM_CONST - logdet - 0.5f * c;
    w[45] = 0.f; w[46] = 0.f; w[47] = 0.f;
}

// ---------------------------------------------------------------------------
// Main kernel. One thread per sample.
//   - f32x2 packed 44-term dots vs shared weight table
//   - online logsumexp over 4 chunks of 16 components (lpc[16] regs only)
//   - pi staged through shared, coalesced LDG.128
//   - last-block finish (threadfence reduction): no third kernel
// ---------------------------------------------------------------------------
__global__ void __launch_bounds__(TPB, 2) mdn_kernel(
    const float* __restrict__ pi,
    const float* __restrict__ target,
    float* __restrict__ out,
    int B) {

    __shared__ float  sW[KCOMP * NW];          // 12 KB
    __shared__ float  sPi[TPB * 33];           // 33 KB (pad 33: conflict-free)
    __shared__ double red[TPB];                //  2 KB
    __shared__ int    sLast;

    const int tid = threadIdx.x;
    const int b0  = blockIdx.x * TPB;
    const int b   = b0 + tid;
    const bool valid = (b < B);

    // weight table -> shared (float4)
    #pragma unroll
    for (int i = tid; i < (KCOMP * NW) / 4; i += TPB)
        reinterpret_cast<float4*>(sW)[i] = reinterpret_cast<const float4*>(g_W)[i];

    // per-sample features, packed as f32x2 pairs
    unsigned long long f2[NF / 2];
    {
        int bb = valid ? b : 0;
        float4 t0 = reinterpret_cast<const float4*>(target)[bb * 2 + 0];
        float4 t1 = reinterpret_cast<const float4*>(target)[bb * 2 + 1];
        float t[DDIM] = {t0.x, t0.y, t0.z, t0.w, t1.x, t1.y, t1.z, t1.w};

        float f[NF];
        int p = 0;
        #pragma unroll
        for (int a = 0; a < DDIM; ++a)
            #pragma unroll
            for (int b2 = a; b2 < DDIM; ++b2) f[p++] = t[a] * t[b2];
        #pragma unroll
        for (int a = 0; a < DDIM; ++a) f[NC + a] = t[a];

        #pragma unroll
        for (int j = 0; j < NF / 2; ++j) f2[j] = pack2(f[2 * j], f[2 * j + 1]);
    }

    float m = -FLT_MAX;
    float S = 0.f;

    #pragma unroll
    for (int c = 0; c < 2; ++c) {
        // ---- stage pi[:, c*32 : c*32+32] for this block's 256 samples ----
        __syncthreads();   // sPi free (and on c==0: sW writes done before use)
        #pragma unroll
        for (int q = tid; q < TPB * 8; q += TPB) {
            int s = q >> 3, e = q & 7;            // sample-in-block, float4-in-row
            int gs = b0 + s;
            float4 v = make_float4(0.f, 0.f, 0.f, 0.f);
            if (gs < B)
                v = reinterpret_cast<const float4*>(pi)[gs * (KCOMP / 4) + c * 8 + e];
            sPi[s * 33 + e * 4 + 0] = v.x;
            sPi[s * 33 + e * 4 + 1] = v.y;
            sPi[s * 33 + e * 4 + 2] = v.z;
            sPi[s * 33 + e * 4 + 3] = v.w;
        }
        __syncthreads();

        #pragma unroll
        for (int h = 0; h < 2; ++h) {
            // ---- lp for 16 components ----
            float lpc[16];
            float cmax = -FLT_MAX;
            #pragma unroll
            for (int kk = 0; kk < 16; ++kk) {
                const int k = c * 32 + h * 16 + kk;
                const ulonglong2* w2 = reinterpret_cast<const ulonglong2*>(sW + k * NW);
                unsigned long long acc0 = 0ull, acc1 = 0ull;   // {0.f,0.f}
                #pragma unroll
                for (int j2 = 0; j2 < 11; ++j2) {
                    ulonglong2 ww = w2[j2];
                    fma2(acc0, f2[2 * j2 + 0], ww.x);
                    fma2(acc1, f2[2 * j2 + 1], ww.y);
                }
                float lp = sum2(acc0) + sum2(acc1) + sW[k * NW + NF];
                lpc[kk] = lp;
                cmax = fmaxf(cmax, lp);
            }

            // ---- online logsumexp fold, pi from shared (conflict-free) ----
            float mn = fmaxf(m, cmax);
            float Sn = S * __expf(m - mn);
            #pragma unroll
            for (int kk = 0; kk < 16; ++kk)
                Sn = fmaf(sPi[tid * 33 + h * 16 + kk] + 1e-10f,
                          __expf(lpc[kk] - mn), Sn);
            m = mn;
            S = Sn;
        }
    }

    float lse = valid ? (m + logf(S)) : 0.f;

    // deterministic in-block tree reduction (double)
    red[tid] = (double)lse;
    __syncthreads();
    #pragma unroll
    for (int s = TPB / 2; s > 0; s >>= 1) {
        if (tid < s) red[tid] += red[tid + s];
        __syncthreads();
    }
    if (tid == 0) {
        g_bsum[blockIdx.x] = red[0];
        __threadfence();
        unsigned t = atomicAdd(&g_done, 1u);
        sLast = (t == gridDim.x - 1);
    }
    __syncthreads();

    // ---- last block finishes: fixed-order sum over g_bsum -> deterministic ----
    if (sLast) {
        double s = 0.0;
        for (int i = tid; i < (int)gridDim.x; i += TPB) s += g_bsum[i];
        red[tid] = s;
        __syncthreads();
        #pragma unroll
        for (int st = TPB / 2; st > 0; st >>= 1) {
            if (tid < st) red[tid] += red[tid + st];
            __syncthreads();
        }
        if (tid == 0) {
            out[0] = (float)(-red[0] / (double)B);
            g_done = 0;            // reset for next graph replay
        }
    }
}

extern "C" void kernel_launch(void* const* d_in, const int* in_sizes, int n_in,
                              void* d_out, int out_size) {
    const float* pi     = (const float*)d_in[0];   // (B, 64)
    const float* mu     = (const float*)d_in[1];   // (64, 8)
    const float* Lc     = (const float*)d_in[2];   // (64, 36)
    const float* target = (const float*)d_in[3];   // (B, 8)

    int B = in_sizes[0] / KCOMP;

    prep_kernel<<<1, KCOMP>>>(mu, Lc);

    int grid = (B + TPB - 1) / TPB;
    if (grid > 4096) grid = 4096;   // B=131072 -> 512 blocks; bound g_bsum
    mdn_kernel<<<grid, TPB>>>(pi, target, (float*)d_out, B);
}

// round 4
// speedup vs baseline: 1.3277x; 1.1643x over previous
#include <cuda_runtime.h>
#include <math.h>
#include <float.h>
#include <stdint.h>

#define KCOMP 64
#define DDIM  8
#define NC    36        // packed lower-tri entries
#define NFEAT 48        // 36 quad + 8 linear + 1 const + 3 zero
#define TPB   256
#define SPB   128       // samples per block (8 warps x 16 rows)
#define NT_TILES 8      // 64 comps / n8
#define KT_TILES 6      // 48 feats / k8

// tril index helper
__device__ __forceinline__ constexpr int TIX(int i, int j) { return i * (i + 1) / 2 + j; }

// scratch (no allocations allowed)
__device__ float4   g_Wfrag[NT_TILES * KT_TILES * 32];   // B fragments, lane-indexed
__device__ double   g_bsum[8192];
__device__ unsigned g_done = 0;

// dynamic smem layout
#define FS_PAD   50                                   // float2 per feature row
#define FS_BYTES (SPB * FS_PAD * 8)                   // 51200
#define WF_CNT   (NT_TILES * KT_TILES * 32)           // 1536 float4
#define SMEM_BYTES (FS_BYTES + WF_CNT * 16)           // 75776

// ---------------------------------------------------------------------------
// tf32 helpers
// ---------------------------------------------------------------------------
__device__ __forceinline__ float2 tf32_split(float x) {
    uint32_t uh, ul;
    asm("cvt.rna.tf32.f32 %0, %1;" : "=r"(uh) : "f"(x));
    float fh = __uint_as_float(uh);
    float r  = x - fh;
    asm("cvt.rna.tf32.f32 %0, %1;" : "=r"(ul) : "f"(r));
    return make_float2(fh, __uint_as_float(ul));
}

__device__ __forceinline__ void mma_tf32(float* c, uint32_t a0, uint32_t a1,
                                         uint32_t a2, uint32_t a3,
                                         uint32_t b0, uint32_t b1) {
    asm volatile(
        "mma.sync.aligned.m16n8k8.row.col.f32.tf32.tf32.f32 "
        "{%0,%1,%2,%3}, {%4,%5,%6,%7}, {%8,%9}, {%0,%1,%2,%3};"
        : "+f"(c[0]), "+f"(c[1]), "+f"(c[2]), "+f"(c[3])
        : "r"(a0), "r"(a1), "r"(a2), "r"(a3), "r"(b0), "r"(b1));
}

// ---------------------------------------------------------------------------
// Preprocess: per component k build the 48-coefficient quadratic form,
// then scatter it into mma B-fragment layout (hi/lo tf32 split) in g_Wfrag.
// lp(t) = sum_j f[j]*w[j],  f = [t_a*t_b (a<=b), t_a, 1, 0,0,0].
// ---------------------------------------------------------------------------
__global__ void __launch_bounds__(64) prep_kernel(const float* __restrict__ mu,
                                                  const float* __restrict__ Lc) {
    int k = threadIdx.x;
    if (k >= KCOMP) return;

    float L[NC];
    #pragma unroll
    for (int i = 0; i < NC; ++i) L[i] = Lc[k * NC + i];

    float logdet = 0.f;
    #pragma unroll
    for (int i = 0; i < DDIM; ++i) logdet += logf(L[TIX(i, i)]);

    float dinv[DDIM];
    #pragma unroll
    for (int i = 0; i < DDIM; ++i) dinv[i] = 1.f / L[TIX(i, i)];

    // A = inv(L), lower triangular, packed tril
    float A[NC];
    #pragma unroll
    for (int j = 0; j < DDIM; ++j) {
        A[TIX(j, j)] = dinv[j];
        #pragma unroll
        for (int i = j + 1; i < DDIM; ++i) {
            float s = 0.f;
            #pragma unroll
            for (int mm = j; mm < i; ++mm) s += L[TIX(i, mm)] * A[TIX(mm, j)];
            A[TIX(i, j)] = -s * dinv[i];
        }
    }

    float mv[DDIM];
    #pragma unroll
    for (int j = 0; j < DDIM; ++j) mv[j] = mu[k * DDIM + j];

    // v = A * mu ; q = A^T v (= P*mu) ; c = |v|^2
    float v[DDIM];
    #pragma unroll
    for (int i = 0; i < DDIM; ++i) {
        float s = 0.f;
        #pragma unroll
        for (int j = 0; j <= i; ++j) s += A[TIX(i, j)] * mv[j];
        v[i] = s;
    }
    float q[DDIM];
    #pragma unroll
    for (int a = 0; a < DDIM; ++a) {
        float s = 0.f;
        #pragma unroll
        for (int i = a; i < DDIM; ++i) s += A[TIX(i, a)] * v[i];
        q[a] = s;
    }
    float c = 0.f;
    #pragma unroll
    for (int i = 0; i < DDIM; ++i) c += v[i] * v[i];

    float w[NFEAT];
    {
        int p = 0;
        #pragma unroll
        for (int a = 0; a < DDIM; ++a) {
            #pragma unroll
            for (int b = a; b < DDIM; ++b) {
                float P = 0.f;
                #pragma unroll
                for (int i = b; i < DDIM; ++i) P += A[TIX(i, a)] * A[TIX(i, b)];
                w[p++] = (a == b) ? -0.5f * P : -P;   // fold factor 2 of off-diag
            }
        }
        #pragma unroll
        for (int a = 0; a < DDIM; ++a) w[NC + a] = q[a];
        const float NORM_CONST = -0.5f * (float)DDIM * 1.8378770664093453f;
        w[44] = NORM_CONST - logdet - 0.5f * c;
        w[45] = 0.f; w[46] = 0.f; w[47] = 0.f;
    }

    // scatter into B-fragment layout:
    // tile = nt*6 + kt, nt = k>>3 ; lane = (k&7)*4 + tig
    // b0 = W[k][8kt+tig], b1 = W[k][8kt+tig+4]; store {hi0,hi1,lo0,lo1}
    int nt   = k >> 3;
    int lane_base = (k & 7) * 4;
    #pragma unroll
    for (int kt = 0; kt < KT_TILES; ++kt) {
        #pragma unroll
        for (int tig = 0; tig < 4; ++tig) {
            float2 s0 = tf32_split(w[8 * kt + tig]);
            float2 s1 = tf32_split(w[8 * kt + tig + 4]);
            g_Wfrag[(nt * KT_TILES + kt) * 32 + lane_base + tig] =
                make_float4(s0.x, s1.x, s0.y, s1.y);
        }
    }
}

// ---------------------------------------------------------------------------
// Main kernel: 256 threads, 128 samples/block.
//   phase 1: threads 0..127 build tf32-split feature rows in smem
//   phase 2: each warp does m16n64k48 via 144 tf32 MMAs (3x split)
//   phase 3: per-row logsumexp with pi, warp-quad shuffles, block reduce
// ---------------------------------------------------------------------------
__global__ void __launch_bounds__(TPB, 2) mdn_kernel(
    const float* __restrict__ pi,
    const float* __restrict__ target,
    float* __restrict__ out,
    int B) {

    extern __shared__ char smem[];
    float2* Fs  = reinterpret_cast<float2*>(smem);                 // [SPB][FS_PAD]
    float4* sWf = reinterpret_cast<float4*>(smem + FS_BYTES);      // [48][32]

    __shared__ double red[TPB];
    __shared__ int    sLast;

    const int tid  = threadIdx.x;
    const int wid  = tid >> 5;
    const int lane = tid & 31;
    const int gid  = lane >> 2;   // 0..7
    const int tig  = lane & 3;    // 0..3

    // ---- cooperative Wfrag load (global -> shared) ----
    #pragma unroll
    for (int i = tid; i < WF_CNT; i += TPB) sWf[i] = g_Wfrag[i];

    // ---- phase 1: features for this block's 128 samples ----
    if (tid < SPB) {
        int s = blockIdx.x * SPB + tid;
        float t[DDIM];
        if (s < B) {
            float4 t0 = reinterpret_cast<const float4*>(target)[s * 2 + 0];
            float4 t1 = reinterpret_cast<const float4*>(target)[s * 2 + 1];
            t[0]=t0.x; t[1]=t0.y; t[2]=t0.z; t[3]=t0.w;
            t[4]=t1.x; t[5]=t1.y; t[6]=t1.z; t[7]=t1.w;
        } else {
            #pragma unroll
            for (int i = 0; i < DDIM; ++i) t[i] = 0.f;
        }

        float2* row = Fs + (size_t)tid * FS_PAD;
        float hp = 0.f, lp_ = 0.f;   // even-slot buffer
        int p = 0;
        auto emit = [&](float val) {
            float2 hl = tf32_split(val);
            if (p & 1) {
                float4 v4 = make_float4(hp, lp_, hl.x, hl.y);
                *reinterpret_cast<float4*>(row + (p - 1)) = v4;
            } else { hp = hl.x; lp_ = hl.y; }
            ++p;
        };
        #pragma unroll
        for (int a = 0; a < DDIM; ++a)
            #pragma unroll
            for (int b2 = a; b2 < DDIM; ++b2) emit(t[a] * t[b2]);
        #pragma unroll
        for (int a = 0; a < DDIM; ++a) emit(t[a]);
        emit(1.0f); emit(0.f); emit(0.f); emit(0.f);
    }
    __syncthreads();

    // ---- phase 2: MMA, warp handles rows [wid*16, wid*16+16) ----
    const int r0loc = wid * 16 + gid;          // local row of c0/c1
    const int r1loc = r0loc + 8;               // local row of c2/c3
    const int r0g   = blockIdx.x * SPB + r0loc;
    const int r1g   = blockIdx.x * SPB + r1loc;

    // pi prefetch (float2 per n-tile per row; one 32B sector per row-quad)
    const float2* pi2 = reinterpret_cast<const float2*>(pi);
    float2 pv0[NT_TILES], pv1[NT_TILES];
    {
        int rr0 = (r0g < B) ? r0g : 0;
        int rr1 = (r1g < B) ? r1g : 0;
        #pragma unroll
        for (int nt = 0; nt < NT_TILES; ++nt) {
            pv0[nt] = pi2[rr0 * 32 + nt * 4 + tig];
            pv1[nt] = pi2[rr1 * 32 + nt * 4 + tig];
        }
    }

    float c[NT_TILES][4];
    #pragma unroll
    for (int nt = 0; nt < NT_TILES; ++nt)
        #pragma unroll
        for (int i = 0; i < 4; ++i) c[nt][i] = 0.f;

    #pragma unroll
    for (int kt = 0; kt < KT_TILES; ++kt) {
        // A fragments (hi/lo) from Fs
        float2 fa0 = Fs[(size_t)r0loc * FS_PAD + 8 * kt + tig];
        float2 fa1 = Fs[(size_t)r1loc * FS_PAD + 8 * kt + tig];
        float2 fa2 = Fs[(size_t)r0loc * FS_PAD + 8 * kt + tig + 4];
        float2 fa3 = Fs[(size_t)r1loc * FS_PAD + 8 * kt + tig + 4];
        uint32_t ah0 = __float_as_uint(fa0.x), al0 = __float_as_uint(fa0.y);
        uint32_t ah1 = __float_as_uint(fa1.x), al1 = __float_as_uint(fa1.y);
        uint32_t ah2 = __float_as_uint(fa2.x), al2 = __float_as_uint(fa2.y);
        uint32_t ah3 = __float_as_uint(fa3.x), al3 = __float_as_uint(fa3.y);

        #pragma unroll
        for (int nt = 0; nt < NT_TILES; ++nt) {
            float4 bw = sWf[(nt * KT_TILES + kt) * 32 + lane];
            uint32_t bh0 = __float_as_uint(bw.x), bh1 = __float_as_uint(bw.y);
            uint32_t bl0 = __float_as_uint(bw.z), bl1 = __float_as_uint(bw.w);
            mma_tf32(c[nt], ah0, ah1, ah2, ah3, bh0, bh1);   // hi*hi
            mma_tf32(c[nt], al0, al1, al2, al3, bh0, bh1);   // lo*hi
            mma_tf32(c[nt], ah0, ah1, ah2, ah3, bl0, bl1);   // hi*lo
        }
    }

    // ---- phase 3: per-row logsumexp with pi ----
    float mx0 = -FLT_MAX, mx1 = -FLT_MAX;
    #pragma unroll
    for (int nt = 0; nt < NT_TILES; ++nt) {
        mx0 = fmaxf(mx0, fmaxf(c[nt][0], c[nt][1]));
        mx1 = fmaxf(mx1, fmaxf(c[nt][2], c[nt][3]));
    }
    mx0 = fmaxf(mx0, __shfl_xor_sync(0xffffffff, mx0, 1));
    mx0 = fmaxf(mx0, __shfl_xor_sync(0xffffffff, mx0, 2));
    mx1 = fmaxf(mx1, __shfl_xor_sync(0xffffffff, mx1, 1));
    mx1 = fmaxf(mx1, __shfl_xor_sync(0xffffffff, mx1, 2));

    float S0 = 0.f, S1 = 0.f;
    #pragma unroll
    for (int nt = 0; nt < NT_TILES; ++nt) {
        S0 = fmaf(pv0[nt].x + 1e-10f, __expf(c[nt][0] - mx0), S0);
        S0 = fmaf(pv0[nt].y + 1e-10f, __expf(c[nt][1] - mx0), S0);
        S1 = fmaf(pv1[nt].x + 1e-10f, __expf(c[nt][2] - mx1), S1);
        S1 = fmaf(pv1[nt].y + 1e-10f, __expf(c[nt][3] - mx1), S1);
    }
    S0 += __shfl_xor_sync(0xffffffff, S0, 1);
    S0 += __shfl_xor_sync(0xffffffff, S0, 2);
    S1 += __shfl_xor_sync(0xffffffff, S1, 1);
    S1 += __shfl_xor_sync(0xffffffff, S1, 2);

    double contrib = 0.0;
    if (tig == 0) {
        if (r0g < B) contrib += (double)(mx0 + logf(S0));
        if (r1g < B) contrib += (double)(mx1 + logf(S1));
    }

    // ---- deterministic block tree reduction ----
    red[tid] = contrib;
    __syncthreads();
    #pragma unroll
    for (int s = TPB / 2; s > 0; s >>= 1) {
        if (tid < s) red[tid] += red[tid + s];
        __syncthreads();
    }
    if (tid == 0) {
        g_bsum[blockIdx.x] = red[0];
        __threadfence();
        unsigned tkt = atomicAdd(&g_done, 1u);
        sLast = (tkt == gridDim.x - 1);
    }
    __syncthreads();

    if (sLast) {
        double s = 0.0;
        for (int i = tid; i < (int)gridDim.x; i += TPB) s += g_bsum[i];
        red[tid] = s;
        __syncthreads();
        #pragma unroll
        for (int st = TPB / 2; st > 0; st >>= 1) {
            if (tid < st) red[tid] += red[tid + st];
            __syncthreads();
        }
        if (tid == 0) {
            out[0] = (float)(-red[0] / (double)B);
            g_done = 0;            // reset for next graph replay
        }
    }
}

extern "C" void kernel_launch(void* const* d_in, const int* in_sizes, int n_in,
                              void* d_out, int out_size) {
    const float* pi     = (const float*)d_in[0];   // (B, 64)
    const float* mu     = (const float*)d_in[1];   // (64, 8)
    const float* Lc     = (const float*)d_in[2];   // (64, 36)
    const float* target = (const float*)d_in[3];   // (B, 8)

    int B = in_sizes[0] / KCOMP;

    cudaFuncSetAttribute(mdn_kernel, cudaFuncAttributeMaxDynamicSharedMemorySize,
                         SMEM_BYTES);

    prep_kernel<<<1, KCOMP>>>(mu, Lc);

    int grid = (B + SPB - 1) / SPB;
    if (grid > 8192) grid = 8192;   // B=131072 -> 1024 blocks; bounds g_bsum
    mdn_kernel<<<grid, TPB, SMEM_BYTES>>>(pi, target, (float*)d_out, B);
}

// round 5
// speedup vs baseline: 1.7143x; 1.2912x over previous
#include <cuda_runtime.h>
#include <cuda_bf16.h>
#include <math.h>
#include <float.h>
#include <stdint.h>
#include <string.h>

#define KCOMP 64
#define DDIM  8
#define NC    36        // packed lower-tri entries
#define TPB   128       // 4 warps
#define SPB   128       // samples per block; each warp owns 32 rows (2 m-tiles)
#define NT    8         // 64 comps / n8
#define KT    3         // 48 feats / k16

// tril index helper
__device__ __forceinline__ constexpr int TIX(int i, int j) { return i * (i + 1) / 2 + j; }

// scratch (no allocations allowed)
__device__ double   g_bsum[8192];
__device__ unsigned g_done = 0;

// dynamic smem layout
#define FS_U4_STRIDE 20                          // uint4 per feature row (320 B)
#define FS_BYTES  (SPB * FS_U4_STRIDE * 16)      // 40960
#define WF_CNT    (NT * KT * 32)                 // 768 uint4
#define WF_BYTES  (WF_CNT * 16)                  // 12288
#define RED_BYTES (TPB * 8)                      // 1024
#define SMEM_BYTES (FS_BYTES + WF_BYTES + RED_BYTES)

// ---------------------------------------------------------------------------
// helpers
// ---------------------------------------------------------------------------
__device__ __forceinline__ uint32_t pack_bf16x2(float a, float b) {
    __nv_bfloat162 h = __floats2bfloat162_rn(a, b);   // .x=a (low), .y=b (high)
    uint32_t u;
    memcpy(&u, &h, 4);
    return u;
}

__device__ __forceinline__ void mma_bf16(float* c, uint32_t a0, uint32_t a1,
                                         uint32_t a2, uint32_t a3,
                                         uint32_t b0, uint32_t b1) {
    asm volatile(
        "mma.sync.aligned.m16n8k16.row.col.f32.bf16.bf16.f32 "
        "{%0,%1,%2,%3}, {%4,%5,%6,%7}, {%8,%9}, {%0,%1,%2,%3};"
        : "+f"(c[0]), "+f"(c[1]), "+f"(c[2]), "+f"(c[3])
        : "r"(a0), "r"(a1), "r"(a2), "r"(a3), "r"(b0), "r"(b1));
}

// ---------------------------------------------------------------------------
// Single fused kernel.
//   A) threads 0..63: rebuild per-component quadratic-form weights w[48],
//      bf16 hi/lo split, write B-fragments directly into smem
//   B) all threads: build one sample row of 48 features (bf16 hi/lo pairs)
//   C) each warp: m32n64k48 via 4-pass bf16 m16n8k16 MMAs
//   D) per-row logsumexp with pi, block tree-reduce, last-block finish
// ---------------------------------------------------------------------------
__global__ void __launch_bounds__(TPB, 4) mdn_kernel(
    const float* __restrict__ pi,
    const float* __restrict__ mu,
    const float* __restrict__ Lc,
    const float* __restrict__ target,
    float* __restrict__ out,
    int B) {

    extern __shared__ char smem[];
    uint4*  FsU4 = reinterpret_cast<uint4*>(smem);                    // [SPB][20]
    uint4*  sWf  = reinterpret_cast<uint4*>(smem + FS_BYTES);         // [24][32]
    double* red  = reinterpret_cast<double*>(smem + FS_BYTES + WF_BYTES);

    const int tid  = threadIdx.x;
    const int wid  = tid >> 5;
    const int lane = tid & 31;
    const int gid  = lane >> 2;   // 0..7
    const int tig  = lane & 3;    // 0..3

    // ================= A) in-block prep (threads 0..63) =================
    if (tid < KCOMP) {
        const int k = tid;

        float L[NC];
        #pragma unroll
        for (int i = 0; i < NC; ++i) L[i] = Lc[k * NC + i];

        float logdet = 0.f;
        #pragma unroll
        for (int i = 0; i < DDIM; ++i) logdet += logf(L[TIX(i, i)]);

        float dinv[DDIM];
        #pragma unroll
        for (int i = 0; i < DDIM; ++i) dinv[i] = 1.f / L[TIX(i, i)];

        // A = inv(L), lower triangular, packed tril
        float A[NC];
        #pragma unroll
        for (int j = 0; j < DDIM; ++j) {
            A[TIX(j, j)] = dinv[j];
            #pragma unroll
            for (int i = j + 1; i < DDIM; ++i) {
                float s = 0.f;
                #pragma unroll
                for (int mm = j; mm < i; ++mm) s += L[TIX(i, mm)] * A[TIX(mm, j)];
                A[TIX(i, j)] = -s * dinv[i];
            }
        }

        float mv[DDIM];
        #pragma unroll
        for (int j = 0; j < DDIM; ++j) mv[j] = mu[k * DDIM + j];

        float v[DDIM];
        #pragma unroll
        for (int i = 0; i < DDIM; ++i) {
            float s = 0.f;
            #pragma unroll
            for (int j = 0; j <= i; ++j) s += A[TIX(i, j)] * mv[j];
            v[i] = s;
        }
        float q[DDIM];
        #pragma unroll
        for (int a = 0; a < DDIM; ++a) {
            float s = 0.f;
            #pragma unroll
            for (int i = a; i < DDIM; ++i) s += A[TIX(i, a)] * v[i];
            q[a] = s;
        }
        float cc = 0.f;
        #pragma unroll
        for (int i = 0; i < DDIM; ++i) cc += v[i] * v[i];

        float w[48];
        {
            int p = 0;
            #pragma unroll
            for (int a = 0; a < DDIM; ++a) {
                #pragma unroll
                for (int b = a; b < DDIM; ++b) {
                    float P = 0.f;
                    #pragma unroll
                    for (int i = b; i < DDIM; ++i) P += A[TIX(i, a)] * A[TIX(i, b)];
                    w[p++] = (a == b) ? -0.5f * P : -P;   // folds 2x of off-diag
                }
            }
            #pragma unroll
            for (int a = 0; a < DDIM; ++a) w[NC + a] = q[a];
            const float NORM_CONST = -0.5f * (float)DDIM * 1.8378770664093453f;
            w[44] = NORM_CONST - logdet - 0.5f * cc;
            w[45] = 0.f; w[46] = 0.f; w[47] = 0.f;
        }

        // bf16 hi/lo split
        float wh[48], wl[48];
        #pragma unroll
        for (int i = 0; i < 48; ++i) {
            float h = __bfloat162float(__float2bfloat16_rn(w[i]));
            wh[i] = h;
            wl[i] = w[i] - h;
        }

        // scatter B fragments: col n = k; lane = (k&7)*4 + tg; tile (k>>3, kt)
        const int nt = k >> 3;
        const int lb = (k & 7) * 4;
        #pragma unroll
        for (int kt = 0; kt < KT; ++kt) {
            #pragma unroll
            for (int tg = 0; tg < 4; ++tg) {
                int kb = 16 * kt + 2 * tg;
                uint4 bw;
                bw.x = pack_bf16x2(wh[kb],     wh[kb + 1]);   // b0 hi
                bw.y = pack_bf16x2(wh[kb + 8], wh[kb + 9]);   // b1 hi
                bw.z = pack_bf16x2(wl[kb],     wl[kb + 1]);   // b0 lo
                bw.w = pack_bf16x2(wl[kb + 8], wl[kb + 9]);   // b1 lo
                sWf[(nt * KT + kt) * 32 + lb + tg] = bw;
            }
        }
    }

    // ================= B) features for row tid =================
    {
        int s = blockIdx.x * SPB + tid;
        float t[DDIM];
        if (s < B) {
            float4 t0 = reinterpret_cast<const float4*>(target)[s * 2 + 0];
            float4 t1 = reinterpret_cast<const float4*>(target)[s * 2 + 1];
            t[0]=t0.x; t[1]=t0.y; t[2]=t0.z; t[3]=t0.w;
            t[4]=t1.x; t[5]=t1.y; t[6]=t1.z; t[7]=t1.w;
        } else {
            #pragma unroll
            for (int i = 0; i < DDIM; ++i) t[i] = 0.f;
        }

        float f[48];
        {
            int p = 0;
            #pragma unroll
            for (int a = 0; a < DDIM; ++a)
                #pragma unroll
                for (int b2 = a; b2 < DDIM; ++b2) f[p++] = t[a] * t[b2];
            #pragma unroll
            for (int a = 0; a < DDIM; ++a) f[NC + a] = t[a];
            f[44] = 1.0f; f[45] = 0.f; f[46] = 0.f; f[47] = 0.f;
        }

        uint32_t hi_u[24], lo_u[24];
        #pragma unroll
        for (int p = 0; p < 24; ++p) {
            float f0 = f[2 * p], f1 = f[2 * p + 1];
            float h0 = __bfloat162float(__float2bfloat16_rn(f0));
            float h1 = __bfloat162float(__float2bfloat16_rn(f1));
            hi_u[p] = pack_bf16x2(h0, h1);
            lo_u[p] = pack_bf16x2(f0 - h0, f1 - h1);
        }

        // store A-fragment slots: slot(kt,tg) = {hi(8kt+tg), lo(8kt+tg),
        //                                        hi(8kt+tg+4), lo(8kt+tg+4)}
        #pragma unroll
        for (int kt = 0; kt < KT; ++kt) {
            #pragma unroll
            for (int tg = 0; tg < 4; ++tg) {
                int p0 = 8 * kt + tg;
                FsU4[tid * FS_U4_STRIDE + kt * 4 + tg] =
                    make_uint4(hi_u[p0], lo_u[p0], hi_u[p0 + 4], lo_u[p0 + 4]);
            }
        }
    }
    __syncthreads();

    // ================= C) MMA: warp owns 32 rows =================
    const int rA = wid * 32 + gid;        // mset0 rows rA, rA+8
    const int rB = rA + 16;               // mset1 rows rB, rB+8

    float c[2][NT][4];
    #pragma unroll
    for (int ms = 0; ms < 2; ++ms)
        #pragma unroll
        for (int nt = 0; nt < NT; ++nt)
            #pragma unroll
            for (int i = 0; i < 4; ++i) c[ms][nt][i] = 0.f;

    #pragma unroll
    for (int kt = 0; kt < KT; ++kt) {
        uint4 A0 = FsU4[(rA)      * FS_U4_STRIDE + kt * 4 + tig]; // a0h,a0l,a2h,a2l
        uint4 A1 = FsU4[(rA + 8)  * FS_U4_STRIDE + kt * 4 + tig]; // a1h,a1l,a3h,a3l
        uint4 A2 = FsU4[(rB)      * FS_U4_STRIDE + kt * 4 + tig];
        uint4 A3 = FsU4[(rB + 8)  * FS_U4_STRIDE + kt * 4 + tig];

        #pragma unroll
        for (int nt = 0; nt < NT; ++nt) {
            uint4 bw = sWf[(nt * KT + kt) * 32 + lane];
            // mset0: 4 passes
            mma_bf16(c[0][nt], A0.x, A1.x, A0.z, A1.z, bw.x, bw.y); // hi*hi
            mma_bf16(c[0][nt], A0.y, A1.y, A0.w, A1.w, bw.x, bw.y); // lo*hi
            mma_bf16(c[0][nt], A0.x, A1.x, A0.z, A1.z, bw.z, bw.w); // hi*lo
            mma_bf16(c[0][nt], A0.y, A1.y, A0.w, A1.w, bw.z, bw.w); // lo*lo
            // mset1
            mma_bf16(c[1][nt], A2.x, A3.x, A2.z, A3.z, bw.x, bw.y);
            mma_bf16(c[1][nt], A2.y, A3.y, A2.w, A3.w, bw.x, bw.y);
            mma_bf16(c[1][nt], A2.x, A3.x, A2.z, A3.z, bw.z, bw.w);
            mma_bf16(c[1][nt], A2.y, A3.y, A2.w, A3.w, bw.z, bw.w);
        }
    }

    // ================= D) per-row logsumexp with pi =================
    const float2* pi2 = reinterpret_cast<const float2*>(pi);
    double contrib = 0.0;

    #pragma unroll
    for (int ms = 0; ms < 2; ++ms) {
        const int r0 = blockIdx.x * SPB + wid * 32 + gid + ms * 16;   // c0/c1 row
        const int r1 = r0 + 8;                                        // c2/c3 row

        float mx0 = -FLT_MAX, mx1 = -FLT_MAX;
        #pragma unroll
        for (int nt = 0; nt < NT; ++nt) {
            mx0 = fmaxf(mx0, fmaxf(c[ms][nt][0], c[ms][nt][1]));
            mx1 = fmaxf(mx1, fmaxf(c[ms][nt][2], c[ms][nt][3]));
        }
        mx0 = fmaxf(mx0, __shfl_xor_sync(0xffffffff, mx0, 1));
        mx0 = fmaxf(mx0, __shfl_xor_sync(0xffffffff, mx0, 2));
        mx1 = fmaxf(mx1, __shfl_xor_sync(0xffffffff, mx1, 1));
        mx1 = fmaxf(mx1, __shfl_xor_sync(0xffffffff, mx1, 2));

        const int rr0 = (r0 < B) ? r0 : 0;
        const int rr1 = (r1 < B) ? r1 : 0;
        float S0 = 0.f, S1 = 0.f;
        #pragma unroll
        for (int nt = 0; nt < NT; ++nt) {
            float2 p0 = pi2[rr0 * 32 + nt * 4 + tig];
            float2 p1 = pi2[rr1 * 32 + nt * 4 + tig];
            S0 = fmaf(p0.x + 1e-10f, __expf(c[ms][nt][0] - mx0), S0);
            S0 = fmaf(p0.y + 1e-10f, __expf(c[ms][nt][1] - mx0), S0);
            S1 = fmaf(p1.x + 1e-10f, __expf(c[ms][nt][2] - mx1), S1);
            S1 = fmaf(p1.y + 1e-10f, __expf(c[ms][nt][3] - mx1), S1);
        }
        S0 += __shfl_xor_sync(0xffffffff, S0, 1);
        S0 += __shfl_xor_sync(0xffffffff, S0, 2);
        S1 += __shfl_xor_sync(0xffffffff, S1, 1);
        S1 += __shfl_xor_sync(0xffffffff, S1, 2);

        if (tig == 0) {
            if (r0 < B) contrib += (double)(mx0 + logf(S0));
            if (r1 < B) contrib += (double)(mx1 + logf(S1));
        }
    }

    // ================= block tree reduction + last-block finish =================
    red[tid] = contrib;
    __syncthreads();
    #pragma unroll
    for (int s = TPB / 2; s > 0; s >>= 1) {
        if (tid < s) red[tid] += red[tid + s];
        __syncthreads();
    }

    __shared__ int sLast;
    if (tid == 0) {
        g_bsum[blockIdx.x] = red[0];
        __threadfence();
        unsigned tkt = atomicAdd(&g_done, 1u);
        sLast = (tkt == gridDim.x - 1);
    }
    __syncthreads();

    if (sLast) {
        double s = 0.0;
        for (int i = tid; i < (int)gridDim.x; i += TPB) s += g_bsum[i];
        red[tid] = s;
        __syncthreads();
        #pragma unroll
        for (int st = TPB / 2; st > 0; st >>= 1) {
            if (tid < st) red[tid] += red[tid + st];
            __syncthreads();
        }
        if (tid == 0) {
            out[0] = (float)(-red[0] / (double)B);
            g_done = 0;            // reset for next graph replay
        }
    }
}

extern "C" void kernel_launch(void* const* d_in, const int* in_sizes, int n_in,
                              void* d_out, int out_size) {
    const float* pi     = (const float*)d_in[0];   // (B, 64)
    const float* mu     = (const float*)d_in[1];   // (64, 8)
    const float* Lc     = (const float*)d_in[2];   // (64, 36)
    const float* target = (const float*)d_in[3];   // (B, 8)

    int B = in_sizes[0] / KCOMP;

    static int configured = 0;
    if (!configured) {
        cudaFuncSetAttribute(mdn_kernel,
                             cudaFuncAttributeMaxDynamicSharedMemorySize,
                             SMEM_BYTES);
        configured = 1;
    }

    int grid = (B + SPB - 1) / SPB;
    if (grid > 8192) grid = 8192;   // B=131072 -> 1024 blocks; bounds g_bsum
    mdn_kernel<<<grid, TPB, SMEM_BYTES>>>(pi, mu, Lc, target, (float*)d_out, B);
}

// round 6
// speedup vs baseline: 2.0260x; 1.1818x over previous
#include <cuda_runtime.h>
#include <cuda_bf16.h>
#include <math.h>
#include <float.h>
#include <stdint.h>
#include <string.h>

#define KCOMP 64
#define DDIM  8
#define NC    36        // packed lower-tri entries
#define TPB   128       // 4 warps
#define SPB   128       // samples per tile; warp owns 32 rows (2 m-tiles)
#define TILES 2         // sample-tiles per block
#define NT    8         // 64 comps / n8
#define KT    3         // 48 feats / k16

// tril index helper
__device__ __forceinline__ constexpr int TIX(int i, int j) { return i * (i + 1) / 2 + j; }

// scratch (no allocations allowed)
__device__ double   g_bsum[8192];
__device__ unsigned g_done = 0;

// smem layout: FS (swizzled feature rows) | WF (B fragments) | red
#define FS_BYTES  (SPB * 16 * 16)            // 32768 (16 uint4 per row)
#define WF_CNT    (NT * KT * 32)             // 768 uint4
#define WF_BYTES  (WF_CNT * 16)              // 12288
#define RED_BYTES (TPB * 8)                  // 1024
#define SMEM_BYTES (FS_BYTES + WF_BYTES + RED_BYTES)

// XOR-swizzled feature-row index (uint4 units). Conflict-free for both the
// store pattern (32 consecutive rows, fixed slot) and load pattern (gid,tig).
__device__ __forceinline__ int fs_idx(int row, int slot) {
    return row * 16 + (slot ^ ((row & 3) << 2) ^ ((row >> 2) & 3));
}

// ---------------------------------------------------------------------------
// helpers
// ---------------------------------------------------------------------------
__device__ __forceinline__ uint32_t pack_bf16x2(float a, float b) {
    __nv_bfloat162 h = __floats2bfloat162_rn(a, b);   // .x=a (low), .y=b (high)
    uint32_t u;
    memcpy(&u, &h, 4);
    return u;
}

// {bf16_trunc(f0), bf16_trunc(f1)} in one PRMT
__device__ __forceinline__ uint32_t prmt_hi(uint32_t a, uint32_t b) {
    uint32_t r;
    asm("prmt.b32 %0, %1, %2, 0x7632;" : "=r"(r) : "r"(a), "r"(b));
    return r;
}

__device__ __forceinline__ void mma_bf16(float* c, uint32_t a0, uint32_t a1,
                                         uint32_t a2, uint32_t a3,
                                         uint32_t b0, uint32_t b1) {
    asm volatile(
        "mma.sync.aligned.m16n8k16.row.col.f32.bf16.bf16.f32 "
        "{%0,%1,%2,%3}, {%4,%5,%6,%7}, {%8,%9}, {%0,%1,%2,%3};"
        : "+f"(c[0]), "+f"(c[1]), "+f"(c[2]), "+f"(c[3])
        : "r"(a0), "r"(a1), "r"(a2), "r"(a3), "r"(b0), "r"(b1));
}

// ---------------------------------------------------------------------------
// Single fused kernel, 2 sample-tiles per block.
//   A) threads 0..63: build per-component weights w[48], bf16 rn hi/lo split,
//      scatter B-fragments into smem (ONCE per block, amortized over 2 tiles)
//   per tile:
//     B) each thread: one sample row of 48 features, truncation hi/lo split
//     C) each warp: m32n64k48 via 3-pass bf16 m16n8k16 MMAs (lo*lo dropped)
//     D) per-row logsumexp with pi -> contrib (accumulated across tiles)
//   E) warp-shuffle reduce, last-block deterministic finish
// ---------------------------------------------------------------------------
__global__ void __launch_bounds__(TPB, 4) mdn_kernel(
    const float* __restrict__ pi,
    const float* __restrict__ mu,
    const float* __restrict__ Lc,
    const float* __restrict__ target,
    float* __restrict__ out,
    int B) {

    extern __shared__ char smem[];
    uint4*  FsU4 = reinterpret_cast<uint4*>(smem);                    // [SPB][16]
    uint4*  sWf  = reinterpret_cast<uint4*>(smem + FS_BYTES);         // [24][32]
    double* red  = reinterpret_cast<double*>(smem + FS_BYTES + WF_BYTES);

    const int tid  = threadIdx.x;
    const int wid  = tid >> 5;
    const int lane = tid & 31;
    const int gid  = lane >> 2;   // 0..7
    const int tig  = lane & 3;    // 0..3

    // ================= A) in-block prep (threads 0..63, once) =================
    if (tid < KCOMP) {
        const int k = tid;

        float L[NC];
        #pragma unroll
        for (int i = 0; i < NC; ++i) L[i] = Lc[k * NC + i];

        float logdet = 0.f;
        #pragma unroll
        for (int i = 0; i < DDIM; ++i) logdet += logf(L[TIX(i, i)]);

        float dinv[DDIM];
        #pragma unroll
        for (int i = 0; i < DDIM; ++i) dinv[i] = 1.f / L[TIX(i, i)];

        float A[NC];
        #pragma unroll
        for (int j = 0; j < DDIM; ++j) {
            A[TIX(j, j)] = dinv[j];
            #pragma unroll
            for (int i = j + 1; i < DDIM; ++i) {
                float s = 0.f;
                #pragma unroll
                for (int mm = j; mm < i; ++mm) s += L[TIX(i, mm)] * A[TIX(mm, j)];
                A[TIX(i, j)] = -s * dinv[i];
            }
        }

        float mv[DDIM];
        #pragma unroll
        for (int j = 0; j < DDIM; ++j) mv[j] = mu[k * DDIM + j];

        float v[DDIM];
        #pragma unroll
        for (int i = 0; i < DDIM; ++i) {
            float s = 0.f;
            #pragma unroll
            for (int j = 0; j <= i; ++j) s += A[TIX(i, j)] * mv[j];
            v[i] = s;
        }
        float q[DDIM];
        #pragma unroll
        for (int a = 0; a < DDIM; ++a) {
            float s = 0.f;
            #pragma unroll
            for (int i = a; i < DDIM; ++i) s += A[TIX(i, a)] * v[i];
            q[a] = s;
        }
        float cc = 0.f;
        #pragma unroll
        for (int i = 0; i < DDIM; ++i) cc += v[i] * v[i];

        float w[48];
        {
            int p = 0;
            #pragma unroll
            for (int a = 0; a < DDIM; ++a) {
                #pragma unroll
                for (int b = a; b < DDIM; ++b) {
                    float P = 0.f;
                    #pragma unroll
                    for (int i = b; i < DDIM; ++i) P += A[TIX(i, a)] * A[TIX(i, b)];
                    w[p++] = (a == b) ? -0.5f * P : -P;   // folds 2x of off-diag
                }
            }
            #pragma unroll
            for (int a = 0; a < DDIM; ++a) w[NC + a] = q[a];
            const float NORM_CONST = -0.5f * (float)DDIM * 1.8378770664093453f;
            w[44] = NORM_CONST - logdet - 0.5f * cc;
            w[45] = 0.f; w[46] = 0.f; w[47] = 0.f;
        }

        // bf16 rn hi/lo split (done once; accuracy matters on W side)
        float wh[48], wl[48];
        #pragma unroll
        for (int i = 0; i < 48; ++i) {
            float h = __bfloat162float(__float2bfloat16_rn(w[i]));
            wh[i] = h;
            wl[i] = w[i] - h;
        }

        // scatter B fragments: col n = k; lane = (k&7)*4 + tg; tile (k>>3, kt)
        const int nt = k >> 3;
        const int lb = (k & 7) * 4;
        #pragma unroll
        for (int kt = 0; kt < KT; ++kt) {
            #pragma unroll
            for (int tg = 0; tg < 4; ++tg) {
                int kb = 16 * kt + 2 * tg;
                uint4 bw;
                bw.x = pack_bf16x2(wh[kb],     wh[kb + 1]);   // b0 hi
                bw.y = pack_bf16x2(wh[kb + 8], wh[kb + 9]);   // b1 hi
                bw.z = pack_bf16x2(wl[kb],     wl[kb + 1]);   // b0 lo
                bw.w = pack_bf16x2(wl[kb + 8], wl[kb + 9]);   // b1 lo
                sWf[(nt * KT + kt) * 32 + lb + tg] = bw;
            }
        }
    }

    double contrib = 0.0;
    const float2* pi2 = reinterpret_cast<const float2*>(pi);

    for (int tile = 0; tile < TILES; ++tile) {
        const int sbase = (blockIdx.x * TILES + tile) * SPB;

        // orders prep/previous-tile MMA reads before FsU4 overwrite
        __syncthreads();

        // ================= B) features for row tid (truncation split) =========
        {
            int s = sbase + tid;
            float t[DDIM];
            if (s < B) {
                float4 t0 = reinterpret_cast<const float4*>(target)[s * 2 + 0];
                float4 t1 = reinterpret_cast<const float4*>(target)[s * 2 + 1];
                t[0]=t0.x; t[1]=t0.y; t[2]=t0.z; t[3]=t0.w;
                t[4]=t1.x; t[5]=t1.y; t[6]=t1.z; t[7]=t1.w;
            } else {
                #pragma unroll
                for (int i = 0; i < DDIM; ++i) t[i] = 0.f;
            }

            float f[48];
            {
                int p = 0;
                #pragma unroll
                for (int a = 0; a < DDIM; ++a)
                    #pragma unroll
                    for (int b2 = a; b2 < DDIM; ++b2) f[p++] = t[a] * t[b2];
                #pragma unroll
                for (int a = 0; a < DDIM; ++a) f[NC + a] = t[a];
                f[44] = 1.0f; f[45] = 0.f; f[46] = 0.f; f[47] = 0.f;
            }

            uint32_t hi_u[24], lo_u[24];
            #pragma unroll
            for (int p = 0; p < 24; ++p) {
                uint32_t u0 = __float_as_uint(f[2 * p]);
                uint32_t u1 = __float_as_uint(f[2 * p + 1]);
                hi_u[p] = prmt_hi(u0, u1);                       // truncated bf16 pair
                float h0 = __uint_as_float(u0 & 0xFFFF0000u);
                float h1 = __uint_as_float(u1 & 0xFFFF0000u);
                lo_u[p] = pack_bf16x2(f[2 * p] - h0, f[2 * p + 1] - h1); // exact resid
            }

            #pragma unroll
            for (int kt = 0; kt < KT; ++kt) {
                #pragma unroll
                for (int tg = 0; tg < 4; ++tg) {
                    int p0 = 8 * kt + tg;
                    FsU4[fs_idx(tid, kt * 4 + tg)] =
                        make_uint4(hi_u[p0], lo_u[p0], hi_u[p0 + 4], lo_u[p0 + 4]);
                }
            }
        }
        __syncthreads();

        // ================= C) MMA: warp owns 32 rows, 3 passes ================
        const int rA = wid * 32 + gid;
        const int rB = rA + 16;

        float c[2][NT][4];
        #pragma unroll
        for (int ms = 0; ms < 2; ++ms)
            #pragma unroll
            for (int nt = 0; nt < NT; ++nt)
                #pragma unroll
                for (int i = 0; i < 4; ++i) c[ms][nt][i] = 0.f;

        #pragma unroll
        for (int kt = 0; kt < KT; ++kt) {
            uint4 A0 = FsU4[fs_idx(rA,      kt * 4 + tig)]; // a0h,a0l,a2h,a2l
            uint4 A1 = FsU4[fs_idx(rA + 8,  kt * 4 + tig)]; // a1h,a1l,a3h,a3l
            uint4 A2 = FsU4[fs_idx(rB,      kt * 4 + tig)];
            uint4 A3 = FsU4[fs_idx(rB + 8,  kt * 4 + tig)];

            #pragma unroll
            for (int nt = 0; nt < NT; ++nt) {
                uint4 bw = sWf[(nt * KT + kt) * 32 + lane];
                // mset0: hi*hi, lo*hi, hi*lo (lo*lo dropped)
                mma_bf16(c[0][nt], A0.x, A1.x, A0.z, A1.z, bw.x, bw.y);
                mma_bf16(c[0][nt], A0.y, A1.y, A0.w, A1.w, bw.x, bw.y);
                mma_bf16(c[0][nt], A0.x, A1.x, A0.z, A1.z, bw.z, bw.w);
                // mset1
                mma_bf16(c[1][nt], A2.x, A3.x, A2.z, A3.z, bw.x, bw.y);
                mma_bf16(c[1][nt], A2.y, A3.y, A2.w, A3.w, bw.x, bw.y);
                mma_bf16(c[1][nt], A2.x, A3.x, A2.z, A3.z, bw.z, bw.w);
            }
        }

        // ================= D) per-row logsumexp with pi =======================
        #pragma unroll
        for (int ms = 0; ms < 2; ++ms) {
            const int r0 = sbase + wid * 32 + gid + ms * 16;   // c0/c1 row
            const int r1 = r0 + 8;                             // c2/c3 row

            float mx0 = -FLT_MAX, mx1 = -FLT_MAX;
            #pragma unroll
            for (int nt = 0; nt < NT; ++nt) {
                mx0 = fmaxf(mx0, fmaxf(c[ms][nt][0], c[ms][nt][1]));
                mx1 = fmaxf(mx1, fmaxf(c[ms][nt][2], c[ms][nt][3]));
            }
            mx0 = fmaxf(mx0, __shfl_xor_sync(0xffffffff, mx0, 1));
            mx0 = fmaxf(mx0, __shfl_xor_sync(0xffffffff, mx0, 2));
            mx1 = fmaxf(mx1, __shfl_xor_sync(0xffffffff, mx1, 1));
            mx1 = fmaxf(mx1, __shfl_xor_sync(0xffffffff, mx1, 2));

            const int rr0 = (r0 < B) ? r0 : 0;
            const int rr1 = (r1 < B) ? r1 : 0;
            float S0 = 0.f, S1 = 0.f;
            #pragma unroll
            for (int nt = 0; nt < NT; ++nt) {
                float2 p0 = pi2[rr0 * 32 + nt * 4 + tig];
                float2 p1 = pi2[rr1 * 32 + nt * 4 + tig];
                S0 = fmaf(p0.x + 1e-10f, __expf(c[ms][nt][0] - mx0), S0);
                S0 = fmaf(p0.y + 1e-10f, __expf(c[ms][nt][1] - mx0), S0);
                S1 = fmaf(p1.x + 1e-10f, __expf(c[ms][nt][2] - mx1), S1);
                S1 = fmaf(p1.y + 1e-10f, __expf(c[ms][nt][3] - mx1), S1);
            }
            S0 += __shfl_xor_sync(0xffffffff, S0, 1);
            S0 += __shfl_xor_sync(0xffffffff, S0, 2);
            S1 += __shfl_xor_sync(0xffffffff, S1, 1);
            S1 += __shfl_xor_sync(0xffffffff, S1, 2);

            if (tig == 0) {
                if (r0 < B) contrib += (double)(mx0 + __logf(S0));
                if (r1 < B) contrib += (double)(mx1 + __logf(S1));
            }
        }
    }

    // ================= E) reduce =================
    #pragma unroll
    for (int off = 16; off > 0; off >>= 1)
        contrib += __shfl_xor_sync(0xffffffff, contrib, off);
    if (lane == 0) red[wid] = contrib;
    __syncthreads();

    __shared__ int sLast;
    if (tid == 0) {
        double s = red[0] + red[1] + red[2] + red[3];
        g_bsum[blockIdx.x] = s;
        __threadfence();
        unsigned tkt = atomicAdd(&g_done, 1u);
        sLast = (tkt == gridDim.x - 1);
    }
    __syncthreads();

    if (sLast) {
        double s = 0.0;
        for (int i = tid; i < (int)gridDim.x; i += TPB) s += g_bsum[i];
        red[tid] = s;
        __syncthreads();
        #pragma unroll
        for (int st = TPB / 2; st > 0; st >>= 1) {
            if (tid < st) red[tid] += red[tid + st];
            __syncthreads();
        }
        if (tid == 0) {
            out[0] = (float)(-red[0] / (double)B);
            g_done = 0;            // reset for next graph replay
        }
    }
}

extern "C" void kernel_launch(void* const* d_in, const int* in_sizes, int n_in,
                              void* d_out, int out_size) {
    const float* pi     = (const float*)d_in[0];   // (B, 64)
    const float* mu     = (const float*)d_in[1];   // (64, 8)
    const float* Lc     = (const float*)d_in[2];   // (64, 36)
    const float* target = (const float*)d_in[3];   // (B, 8)

    int B = in_sizes[0] / KCOMP;

    static int configured = 0;
    if (!configured) {
        cudaFuncSetAttribute(mdn_kernel,
                             cudaFuncAttributeMaxDynamicSharedMemorySize,
                             SMEM_BYTES);
        configured = 1;
    }

    int tiles = (B + SPB - 1) / SPB;
    int grid  = (tiles + TILES - 1) / TILES;      // B=131072 -> 512 blocks
    if (grid > 8192) grid = 8192;                 // bounds g_bsum
    mdn_kernel<<<grid, TPB, SMEM_BYTES>>>(pi, mu, Lc, target, (float*)d_out, B);
}